// round 4
// baseline (speedup 1.0000x reference)
#include <cuda_runtime.h>
#include <cuda_bf16.h>
#include <math.h>

// ============================================================================
// Problem: b=8, c=128, h=w=128, heads=8, hd=16, kvlen = 64+16+4+1 = 85
// ============================================================================

#define NB   8
#define NC   128
#define NH   8
#define HD   16
#define KVL  85
#define KVS  (KVL * HD)          // 1360

// device scratch (allocation-free rule: __device__ globals)
__device__ __align__(16) float d_tab[128 * 64];   // tab[y*64+j]
__device__ __align__(16) float d_tabT[64 * 128];  // tabT[j*128+p] = tab[p*64+j]
__device__ __align__(16) float d_tabR[8 * 64];    // tabR[bin*64+j] = sum_{t<16} tab[(16bin+t)*64+j]
__device__ __align__(16) float d_y1[NB * NC * KVL];
__device__ __align__(16) float d_k[NB * NH * KVS];
__device__ __align__(16) float d_v[NB * NH * KVS];

typedef unsigned long long u64;

// ----------------------------------------------------------------------------
// f32x2 packed math (Blackwell FFMA2: 2x fp32 FMA per issue)
// ----------------------------------------------------------------------------
__device__ __forceinline__ u64 fma2(u64 a, u64 b, u64 c) {
    u64 d;
    asm("fma.rn.f32x2 %0, %1, %2, %3;" : "=l"(d) : "l"(a), "l"(b), "l"(c));
    return d;
}
__device__ __forceinline__ u64 mul2(u64 a, u64 b) {
    u64 d;
    asm("mul.rn.f32x2 %0, %1, %2;" : "=l"(d) : "l"(a), "l"(b));
    return d;
}
__device__ __forceinline__ u64 splat2(float x) {
    u64 d;
    asm("mov.b64 %0, {%1, %1};" : "=l"(d) : "f"(x));
    return d;
}
__device__ __forceinline__ u64 pack2(float lo, float hi) {
    u64 d;
    asm("mov.b64 %0, {%1, %2};" : "=l"(d) : "f"(lo), "f"(hi));
    return d;
}
__device__ __forceinline__ void unpack2(u64 v, float& lo, float& hi) {
    asm("mov.b64 {%0, %1}, %2;" : "=f"(lo), "=f"(hi) : "l"(v));
}

// ----------------------------------------------------------------------------
// K0: pos-enc tables. inv[i] = 10000^(-(2i)/64)
// ----------------------------------------------------------------------------
__global__ void k_tables() {
    int idx = blockIdx.x * 256 + threadIdx.x;
    if (idx < 8192) {
        int yv = idx >> 6, j = idx & 63, i = j & 31;
        float inv = powf(10000.0f, -(2.0f * (float)i) / 64.0f);
        float a = (float)yv * inv;
        d_tab[idx] = (j < 32) ? sinf(a) : cosf(a);
    } else if (idx < 16384) {
        int e = idx - 8192;
        int j = e >> 7, p = e & 127, i = j & 31;
        float inv = powf(10000.0f, -(2.0f * (float)i) / 64.0f);
        float a = (float)p * inv;
        d_tabT[e] = (j < 32) ? sinf(a) : cosf(a);
    } else if (idx < 16896) {
        int e = idx - 16384;
        int bin = e >> 6, j = e & 63, i = j & 31;
        float inv = powf(10000.0f, -(2.0f * (float)i) / 64.0f);
        float s = 0.0f;
        for (int t = 0; t < 16; ++t) {
            float a = (float)(bin * 16 + t) * inv;
            s += (j < 32) ? sinf(a) : cosf(a);
        }
        d_tabR[e] = s;
    }
}

// ----------------------------------------------------------------------------
// K1: per-(b,c): pool x to 8x8 means, add analytic pos-enc bin sums, derive
// 4x4/2x2/1x1 (nested means), depthwise 3x3 SAME conv -> y1[b][c][0..84]
// ----------------------------------------------------------------------------
__global__ void k_pool_dw(const float* __restrict__ x, const float* __restrict__ dw) {
    __shared__ float pm[64];
    __shared__ float g4[16];
    __shared__ float g2[4];
    __shared__ float g1[1];
    int tid = threadIdx.x;
    int b = blockIdx.x >> 7, c = blockIdx.x & 127;

    if (tid < 64) pm[tid] = 0.0f;
    __syncthreads();

    int r = tid >> 1, hf = tid & 1;     // row 0..127, column half
    const float4* xr = (const float4*)(x + ((size_t)(b * NC + c) << 14) + (r << 7) + (hf << 6));
    float sbin[4] = {0.0f, 0.0f, 0.0f, 0.0f};
#pragma unroll
    for (int q = 0; q < 16; ++q) {
        float4 v = xr[q];
        sbin[q >> 2] += (v.x + v.y) + (v.z + v.w);
    }
    int by = r >> 4;
#pragma unroll
    for (int t = 0; t < 4; ++t) atomicAdd(&pm[by * 8 + hf * 4 + t], sbin[t]);
    __syncthreads();

    if (tid < 64) {
        int byy = tid >> 3, bx = tid & 7;
        float pe = (c < 64) ? d_tabR[byy * 64 + c] : d_tabR[bx * 64 + (c - 64)];
        pm[tid] = (pm[tid] + 16.0f * pe) * (1.0f / 256.0f);
    }
    __syncthreads();

    if (tid < 16) {
        int i = tid >> 2, j = tid & 3;
        g4[tid] = 0.25f * (pm[(2 * i) * 8 + 2 * j] + pm[(2 * i) * 8 + 2 * j + 1] +
                           pm[(2 * i + 1) * 8 + 2 * j] + pm[(2 * i + 1) * 8 + 2 * j + 1]);
    } else if (tid < 20) {
        int t = tid - 16;
        int i = t >> 1, j = t & 1;
        float s = 0.0f;
        for (int yy = 0; yy < 4; ++yy)
            for (int xq = 0; xq < 4; ++xq) s += pm[(4 * i + yy) * 8 + 4 * j + xq];
        g2[t] = s * (1.0f / 16.0f);
    } else if (tid == 20) {
        float s = 0.0f;
        for (int q = 0; q < 64; ++q) s += pm[q];
        g1[0] = s * (1.0f / 64.0f);
    }
    __syncthreads();

    if (tid < KVL) {
        float wv[9];
#pragma unroll
        for (int q = 0; q < 9; ++q) wv[q] = dw[c * 9 + q];
        const float* g;
        int s, ly, lx;
        if (tid < 64)      { g = pm; s = 8; ly = tid >> 3;        lx = tid & 7; }
        else if (tid < 80) { int t = tid - 64; g = g4; s = 4; ly = t >> 2; lx = t & 3; }
        else if (tid < 84) { int t = tid - 80; g = g2; s = 2; ly = t >> 1; lx = t & 1; }
        else               { g = g1; s = 1; ly = 0; lx = 0; }
        float a = 0.0f;
#pragma unroll
        for (int ky = 0; ky < 3; ++ky) {
            int iy = ly + ky - 1;
            bool oky = (iy >= 0) && (iy < s);
#pragma unroll
            for (int kx = 0; kx < 3; ++kx) {
                int ix = lx + kx - 1;
                if (oky && ix >= 0 && ix < s) a += g[iy * s + ix] * wv[ky * 3 + kx];
            }
        }
        d_y1[(b * NC + c) * KVL + tid] = a;
    }
}

// ----------------------------------------------------------------------------
// K2: per-(b,row): pointwise 1x1 -> LayerNorm(c) -> exact GELU -> KV projection
// ----------------------------------------------------------------------------
__global__ void k_pw_ln_kv(const float* __restrict__ pw, const float* __restrict__ lnw,
                           const float* __restrict__ lnb, const float* __restrict__ Wkv) {
    __shared__ float ycol[128];
    __shared__ float zs[128];
    __shared__ float red[2];
    int tid = threadIdx.x;
    int b = blockIdx.x / KVL;
    int row = blockIdx.x - b * KVL;

    if (tid < 128) ycol[tid] = d_y1[(b * NC + tid) * KVL + row];
    __syncthreads();

    if (tid < 128) {
        float a = 0.0f;
        const float* w = pw + tid * 128;
#pragma unroll 8
        for (int ci = 0; ci < 128; ++ci) a += w[ci] * ycol[ci];
        zs[tid] = a;
    }
    __syncthreads();

    if (tid < 32) {
        float s = zs[tid] + zs[tid + 32] + zs[tid + 64] + zs[tid + 96];
#pragma unroll
        for (int o = 16; o; o >>= 1) s += __shfl_xor_sync(0xffffffffu, s, o);
        if (tid == 0) red[0] = s * (1.0f / 128.0f);
    }
    __syncthreads();
    float mu = red[0];
    if (tid < 32) {
        float s = 0.0f;
#pragma unroll
        for (int q = 0; q < 4; ++q) { float dd = zs[tid + 32 * q] - mu; s += dd * dd; }
#pragma unroll
        for (int o = 16; o; o >>= 1) s += __shfl_xor_sync(0xffffffffu, s, o);
        if (tid == 0) red[1] = s * (1.0f / 128.0f);
    }
    __syncthreads();
    float rstd = rsqrtf(red[1] + 1e-5f);
    if (tid < 128) {
        float zn = (zs[tid] - mu) * rstd * lnw[tid] + lnb[tid];
        zs[tid] = 0.5f * zn * (1.0f + erff(zn * 0.70710678118654752f));
    }
    __syncthreads();

    float a = 0.0f;
    const float* w = Wkv + tid * 128;
#pragma unroll 8
    for (int ci = 0; ci < 128; ++ci) a += w[ci] * zs[ci];
    int m = (tid >> 4) & 7, d = tid & 15;
    float* dst = (tid < 128) ? d_k : d_v;
    dst[((size_t)(b * NH + m) * KVL + row) * HD + d] = a;
}

// ----------------------------------------------------------------------------
// K3: fused main kernel: one block per (b, image row y) = 128 query pixels
// thread layout: th = tid>>5 (head / 16-channel tile), tx = tid&31 (4 pixels)
// B swizzle: XOR in-row, column = o ^ (c & 28) — wraps within 0..127, no
// cross-row collision. GEMM B reads are warp-broadcast (th uniform per warp).
// ----------------------------------------------------------------------------
#define STR   132
#define SWZ(c) ((c) & 28)
#define BS_SZ (128 * STR)
#define OFF_B (128 * STR)              // 16896
#define OFF_K (OFF_B + BS_SZ)          // 33792
#define OFF_V (OFF_K + NH * KVS)       // 44672
#define SMEMF (OFF_V + NH * KVS)       // 55552 floats = 222208 bytes

// out[x][o] = sum_c A[c*STR+x] * B[c][o^swz(c)]; acc[op][xi] packs (o=2op,2op+1)
__device__ __forceinline__ void gemm128(const float* __restrict__ A,
                                        const float* __restrict__ B,
                                        int tx, int th, u64 acc[8][4]) {
#pragma unroll
    for (int op = 0; op < 8; ++op)
#pragma unroll
        for (int xi = 0; xi < 4; ++xi) acc[op][xi] = 0ull;
    const float* ap = A + tx * 4;
    int base = th * 16;
#pragma unroll 4
    for (int k = 0; k < 128; ++k) {
        float4 av = *(const float4*)(ap + k * STR);
        const float* brow = B + k * STR;
        int s = SWZ(k);
        ulonglong2 b01 = *(const ulonglong2*)(brow + ((base     ) ^ s));
        ulonglong2 b23 = *(const ulonglong2*)(brow + ((base +  4) ^ s));
        ulonglong2 b45 = *(const ulonglong2*)(brow + ((base +  8) ^ s));
        ulonglong2 b67 = *(const ulonglong2*)(brow + ((base + 12) ^ s));
        u64 a0 = splat2(av.x), a1 = splat2(av.y), a2 = splat2(av.z), a3 = splat2(av.w);
        u64 bb[8] = {b01.x, b01.y, b23.x, b23.y, b45.x, b45.y, b67.x, b67.y};
#pragma unroll
        for (int op = 0; op < 8; ++op) {
            acc[op][0] = fma2(bb[op], a0, acc[op][0]);
            acc[op][1] = fma2(bb[op], a1, acc[op][1]);
            acc[op][2] = fma2(bb[op], a2, acc[op][2]);
            acc[op][3] = fma2(bb[op], a3, acc[op][3]);
        }
    }
}

__device__ __forceinline__ void load_w_swz(const float* __restrict__ W, float* __restrict__ Bs,
                                           int tid) {
    const float4* w4 = (const float4*)W;
    for (int i = tid; i < 4096; i += 256) {
        int o = i >> 5, cq = (i & 31) * 4;
        float4 w = w4[i];
        int col = o ^ SWZ(cq);   // (cq+d)&28 == cq&28 for d<4
        Bs[(cq    ) * STR + col] = w.x;
        Bs[(cq + 1) * STR + col] = w.y;
        Bs[(cq + 2) * STR + col] = w.z;
        Bs[(cq + 3) * STR + col] = w.w;
    }
}

__global__ void __launch_bounds__(256, 1)
k_main(const float* __restrict__ x, const float* __restrict__ Wq,
       const float* __restrict__ Wproj, const float* __restrict__ bproj,
       float* __restrict__ out) {
    extern __shared__ float sm[];
    float* As = sm;                // Xp (channel-major) then O
    float* Bs = sm + OFF_B;        // Wq(sw) -> Q[o][x] -> Wproj(sw)
    float* Ks = sm + OFF_K;
    float* Vs = sm + OFF_V;
    int tid = threadIdx.x;
    int b = blockIdx.x >> 7;
    int y = blockIdx.x & 127;

    {   // K/V for this batch
        const float4* kg = (const float4*)(d_k + (size_t)b * NH * KVS);
        const float4* vg = (const float4*)(d_v + (size_t)b * NH * KVS);
        float4* k4 = (float4*)Ks;
        float4* v4 = (float4*)Vs;
        for (int i = tid; i < NH * KVS / 4; i += 256) { k4[i] = kg[i]; v4[i] = vg[i]; }
    }
    {   // Xp row (x + posenc), channel-major As[c*STR + xx]
        const float4* xr = (const float4*)(x + (((size_t)b * NC) << 14) + (y << 7));
        for (int i = tid; i < 4096; i += 256) {
            int c = i >> 5, xq = i & 31;
            float4 v = xr[c * 4096 + xq];
            if (c < 64) {
                float pe = d_tab[y * 64 + c];
                v.x += pe; v.y += pe; v.z += pe; v.w += pe;
            } else {
                float4 p = ((const float4*)d_tabT)[(c - 64) * 32 + xq];
                v.x += p.x; v.y += p.y; v.z += p.z; v.w += p.w;
            }
            *(float4*)(As + c * STR + xq * 4) = v;
        }
    }
    load_w_swz(Wq, Bs, tid);
    __syncthreads();

    int tx = tid & 31, th = tid >> 5;
    u64 acc[8][4];

    // ---- Q-GEMM ----
    gemm128(As, Bs, tx, th, acc);
    __syncthreads();   // all Xp / Wq reads done

    // spill Q (pre-scaled by hd^-0.5 = 0.25) into this thread's own Bs cells
    {
        u64 s4 = splat2(0.25f);
#pragma unroll
        for (int op = 0; op < 8; ++op)
#pragma unroll
            for (int xi = 0; xi < 4; ++xi) {
                float lo, hi;
                unpack2(mul2(acc[op][xi], s4), lo, hi);
                Bs[(th * 16 + 2 * op) * STR + tx * 4 + xi] = lo;
                Bs[(th * 16 + 2 * op + 1) * STR + tx * 4 + xi] = hi;
            }
    }
    // no sync: each thread reads back only its own Q cells

    const u64* kb = (const u64*)(Ks + th * KVS);
    const u64* vb = (const u64*)(Vs + th * KVS);
    const float* Qs = Bs;
    float* Os = As;

    // ---- attention (single-pass softmax; logits are tiny, no max needed) ----
    for (int xi = 0; xi < 4; ++xi) {
        int xx = tx * 4 + xi;
        u64 q2[8];
#pragma unroll
        for (int op = 0; op < 8; ++op)
            q2[op] = pack2(Qs[(th * 16 + 2 * op) * STR + xx],
                           Qs[(th * 16 + 2 * op + 1) * STR + xx]);
        u64 oa[8];
#pragma unroll
        for (int i = 0; i < 8; ++i) oa[i] = 0ull;
        float sA = 0.0f, sB = 0.0f;
#pragma unroll 5
        for (int j = 0; j < KVL; ++j) {
            const float* kf = (const float*)(kb + j * 8);
            ulonglong2 k01 = *(const ulonglong2*)(kf);
            ulonglong2 k23 = *(const ulonglong2*)(kf + 4);
            ulonglong2 k45 = *(const ulonglong2*)(kf + 8);
            ulonglong2 k67 = *(const ulonglong2*)(kf + 12);
            u64 a0 = mul2(q2[0], k01.x);
            u64 a1 = mul2(q2[1], k01.y);
            a0 = fma2(q2[2], k23.x, a0);  a1 = fma2(q2[3], k23.y, a1);
            a0 = fma2(q2[4], k45.x, a0);  a1 = fma2(q2[5], k45.y, a1);
            a0 = fma2(q2[6], k67.x, a0);  a1 = fma2(q2[7], k67.y, a1);
            float l0, h0, l1, h1;
            unpack2(a0, l0, h0); unpack2(a1, l1, h1);
            float e = __expf((l0 + h0) + (l1 + h1));
            if (j & 1) sB += e; else sA += e;
            u64 pj = splat2(e);
            const float* vf = (const float*)(vb + j * 8);
            ulonglong2 v01 = *(const ulonglong2*)(vf);
            ulonglong2 v23 = *(const ulonglong2*)(vf + 4);
            ulonglong2 v45 = *(const ulonglong2*)(vf + 8);
            ulonglong2 v67 = *(const ulonglong2*)(vf + 12);
            oa[0] = fma2(pj, v01.x, oa[0]);  oa[1] = fma2(pj, v01.y, oa[1]);
            oa[2] = fma2(pj, v23.x, oa[2]);  oa[3] = fma2(pj, v23.y, oa[3]);
            oa[4] = fma2(pj, v45.x, oa[4]);  oa[5] = fma2(pj, v45.y, oa[5]);
            oa[6] = fma2(pj, v67.x, oa[6]);  oa[7] = fma2(pj, v67.y, oa[7]);
        }
        float inv = 1.0f / (sA + sB);
#pragma unroll
        for (int i = 0; i < 8; ++i) {
            float lo, hi;
            unpack2(oa[i], lo, hi);
            Os[(th * 16 + 2 * i) * STR + xx] = lo * inv;
            Os[(th * 16 + 2 * i + 1) * STR + xx] = hi * inv;
        }
    }
    __syncthreads();   // Os complete; Q (Bs) dead

    // ---- out-proj GEMM ----
    load_w_swz(Wproj, Bs, tid);
    __syncthreads();
    gemm128(Os, Bs, tx, th, acc);

    float* og = out + (((size_t)b * NC) << 14) + (y << 7) + tx * 4;
#pragma unroll
    for (int op = 0; op < 8; ++op) {
        float b0 = bproj[th * 16 + 2 * op];
        float b1 = bproj[th * 16 + 2 * op + 1];
        float l0, h0, l1, h1, l2, h2, l3, h3;
        unpack2(acc[op][0], l0, h0); unpack2(acc[op][1], l1, h1);
        unpack2(acc[op][2], l2, h2); unpack2(acc[op][3], l3, h3);
        *(float4*)(og + ((size_t)(th * 16 + 2 * op) << 14)) =
            make_float4(l0 + b0, l1 + b0, l2 + b0, l3 + b0);
        *(float4*)(og + ((size_t)(th * 16 + 2 * op + 1) << 14)) =
            make_float4(h0 + b1, h1 + b1, h2 + b1, h3 + b1);
    }
}

// ----------------------------------------------------------------------------
extern "C" void kernel_launch(void* const* d_in, const int* in_sizes, int n_in,
                              void* d_out, int out_size) {
    const float* x     = (const float*)d_in[0];
    const float* Wq    = (const float*)d_in[1];
    const float* Wkv   = (const float*)d_in[2];
    const float* Wproj = (const float*)d_in[3];
    const float* bproj = (const float*)d_in[4];
    const float* dw    = (const float*)d_in[5];
    const float* pw    = (const float*)d_in[6];
    const float* lnw   = (const float*)d_in[7];
    const float* lnb   = (const float*)d_in[8];
    float* out = (float*)d_out;

    cudaFuncSetAttribute(k_main, cudaFuncAttributeMaxDynamicSharedMemorySize,
                         SMEMF * (int)sizeof(float));

    k_tables<<<66, 256>>>();
    k_pool_dw<<<NB * NC, 256>>>(x, dw);
    k_pw_ln_kv<<<NB * KVL, 256>>>(pw, lnw, lnb, Wkv);
    k_main<<<NB * 128, 256, SMEMF * sizeof(float)>>>(x, Wq, Wproj, bproj, out);
}

// round 5
// speedup vs baseline: 1.3931x; 1.3931x over previous
#include <cuda_runtime.h>
#include <cuda_bf16.h>
#include <math.h>

// ============================================================================
// Problem: b=8, c=128, h=w=128, heads=8, hd=16, kvlen = 64+16+4+1 = 85
// ============================================================================

#define NB   8
#define NC   128
#define NH   8
#define HD   16
#define KVL  85
#define KVS  (KVL * HD)          // 1360

// device scratch (allocation-free rule: __device__ globals)
__device__ __align__(16) float d_tab[128 * 64];   // tab[y*64+j]
__device__ __align__(16) float d_tabT[64 * 128];  // tabT[j*128+p] = tab[p*64+j]
__device__ __align__(16) float d_tabR[8 * 64];    // tabR[bin*64+j] = sum_{t<16} tab[(16bin+t)*64+j]
__device__ __align__(16) float d_y1[NB * KVL * NC];   // TRANSPOSED: [b][row][c]
__device__ __align__(16) float d_pwT[128 * 128];      // pwT[ci][o]
__device__ __align__(16) float d_WkvT[128 * 256];     // WkvT[ci][o]
__device__ __align__(16) float d_k[NB * NH * KVS];
__device__ __align__(16) float d_v[NB * NH * KVS];

typedef unsigned long long u64;

// ----------------------------------------------------------------------------
// f32x2 packed math (Blackwell FFMA2: 2x fp32 FMA per issue)
// ----------------------------------------------------------------------------
__device__ __forceinline__ u64 fma2(u64 a, u64 b, u64 c) {
    u64 d;
    asm("fma.rn.f32x2 %0, %1, %2, %3;" : "=l"(d) : "l"(a), "l"(b), "l"(c));
    return d;
}
__device__ __forceinline__ u64 mul2(u64 a, u64 b) {
    u64 d;
    asm("mul.rn.f32x2 %0, %1, %2;" : "=l"(d) : "l"(a), "l"(b));
    return d;
}
__device__ __forceinline__ u64 splat2(float x) {
    u64 d;
    asm("mov.b64 %0, {%1, %1};" : "=l"(d) : "f"(x));
    return d;
}
__device__ __forceinline__ void unpack2(u64 v, float& lo, float& hi) {
    asm("mov.b64 {%0, %1}, %2;" : "=f"(lo), "=f"(hi) : "l"(v));
}

// ----------------------------------------------------------------------------
// K0: pos-enc tables + weight transposes. inv[i] = 10000^(-(2i)/64)
// ----------------------------------------------------------------------------
__global__ void k_tables(const float* __restrict__ pw, const float* __restrict__ Wkv) {
    int idx = blockIdx.x * 256 + threadIdx.x;
    if (idx < 8192) {
        int yv = idx >> 6, j = idx & 63, i = j & 31;
        float inv = powf(10000.0f, -(2.0f * (float)i) / 64.0f);
        float a = (float)yv * inv;
        d_tab[idx] = (j < 32) ? sinf(a) : cosf(a);
    } else if (idx < 16384) {
        int e = idx - 8192;
        int j = e >> 7, p = e & 127, i = j & 31;
        float inv = powf(10000.0f, -(2.0f * (float)i) / 64.0f);
        float a = (float)p * inv;
        d_tabT[e] = (j < 32) ? sinf(a) : cosf(a);
    } else if (idx < 16896) {
        int e = idx - 16384;
        int bin = e >> 6, j = e & 63, i = j & 31;
        float inv = powf(10000.0f, -(2.0f * (float)i) / 64.0f);
        float s = 0.0f;
        for (int t = 0; t < 16; ++t) {
            float a = (float)(bin * 16 + t) * inv;
            s += (j < 32) ? sinf(a) : cosf(a);
        }
        d_tabR[e] = s;
    } else if (idx < 16896 + 16384) {
        int e = idx - 16896;                 // e = ci*128 + o
        int ci = e >> 7, o = e & 127;
        d_pwT[e] = pw[o * 128 + ci];
    } else if (idx < 16896 + 16384 + 32768) {
        int e = idx - (16896 + 16384);       // e = ci*256 + o
        int ci = e >> 8, o = e & 255;
        d_WkvT[e] = Wkv[o * 128 + ci];
    }
}

// ----------------------------------------------------------------------------
// K1: per-(b,c): pool x to 8x8 means, add analytic pos-enc bin sums, derive
// 4x4/2x2/1x1 (nested means), depthwise 3x3 SAME conv -> y1[b][row][c]
// ----------------------------------------------------------------------------
__global__ void k_pool_dw(const float* __restrict__ x, const float* __restrict__ dw) {
    __shared__ float pm[64];
    __shared__ float g4[16];
    __shared__ float g2[4];
    __shared__ float g1[1];
    int tid = threadIdx.x;
    int b = blockIdx.x >> 7, c = blockIdx.x & 127;

    if (tid < 64) pm[tid] = 0.0f;
    __syncthreads();

    int r = tid >> 1, hf = tid & 1;     // row 0..127, column half
    const float4* xr = (const float4*)(x + ((size_t)(b * NC + c) << 14) + (r << 7) + (hf << 6));
    float sbin[4] = {0.0f, 0.0f, 0.0f, 0.0f};
#pragma unroll
    for (int q = 0; q < 16; ++q) {
        float4 v = xr[q];
        sbin[q >> 2] += (v.x + v.y) + (v.z + v.w);
    }
    int by = r >> 4;
#pragma unroll
    for (int t = 0; t < 4; ++t) atomicAdd(&pm[by * 8 + hf * 4 + t], sbin[t]);
    __syncthreads();

    if (tid < 64) {
        int byy = tid >> 3, bx = tid & 7;
        float pe = (c < 64) ? d_tabR[byy * 64 + c] : d_tabR[bx * 64 + (c - 64)];
        pm[tid] = (pm[tid] + 16.0f * pe) * (1.0f / 256.0f);
    }
    __syncthreads();

    if (tid < 16) {
        int i = tid >> 2, j = tid & 3;
        g4[tid] = 0.25f * (pm[(2 * i) * 8 + 2 * j] + pm[(2 * i) * 8 + 2 * j + 1] +
                           pm[(2 * i + 1) * 8 + 2 * j] + pm[(2 * i + 1) * 8 + 2 * j + 1]);
    } else if (tid < 20) {
        int t = tid - 16;
        int i = t >> 1, j = t & 1;
        float s = 0.0f;
        for (int yy = 0; yy < 4; ++yy)
            for (int xq = 0; xq < 4; ++xq) s += pm[(4 * i + yy) * 8 + 4 * j + xq];
        g2[t] = s * (1.0f / 16.0f);
    } else if (tid == 20) {
        float s = 0.0f;
        for (int q = 0; q < 64; ++q) s += pm[q];
        g1[0] = s * (1.0f / 64.0f);
    }
    __syncthreads();

    if (tid < KVL) {
        float wv[9];
#pragma unroll
        for (int q = 0; q < 9; ++q) wv[q] = dw[c * 9 + q];
        const float* g;
        int s, ly, lx;
        if (tid < 64)      { g = pm; s = 8; ly = tid >> 3;        lx = tid & 7; }
        else if (tid < 80) { int t = tid - 64; g = g4; s = 4; ly = t >> 2; lx = t & 3; }
        else if (tid < 84) { int t = tid - 80; g = g2; s = 2; ly = t >> 1; lx = t & 1; }
        else               { g = g1; s = 1; ly = 0; lx = 0; }
        float a = 0.0f;
#pragma unroll
        for (int ky = 0; ky < 3; ++ky) {
            int iy = ly + ky - 1;
            bool oky = (iy >= 0) && (iy < s);
#pragma unroll
            for (int kx = 0; kx < 3; ++kx) {
                int ix = lx + kx - 1;
                if (oky && ix >= 0 && ix < s) a += g[iy * s + ix] * wv[ky * 3 + kx];
            }
        }
        d_y1[((size_t)b * KVL + tid) * NC + c] = a;   // transposed store
    }
}

// ----------------------------------------------------------------------------
// K2: per-(b,row): pointwise 1x1 -> LayerNorm(c) -> exact GELU -> KV projection
// All weight reads coalesced via pre-transposed d_pwT / d_WkvT.
// ----------------------------------------------------------------------------
__global__ void k_pw_ln_kv(const float* __restrict__ lnw, const float* __restrict__ lnb) {
    __shared__ float ycol[128];
    __shared__ float part[256];
    __shared__ float zs[128];
    __shared__ float red[2];
    int tid = threadIdx.x;
    int b = blockIdx.x / KVL;
    int row = blockIdx.x - b * KVL;

    if (tid < 128) ycol[tid] = d_y1[((size_t)b * KVL + row) * NC + tid];
    __syncthreads();

    // pointwise: split ci-range over the two thread halves
    {
        int o = tid & 127;
        int half = tid >> 7;                 // 0: ci 0..63, 1: ci 64..127
        const float* wc = d_pwT + (half << 6) * 128 + o;
        const float* yc = ycol + (half << 6);
        float a = 0.0f;
#pragma unroll 8
        for (int ci = 0; ci < 64; ++ci) a += wc[ci * 128] * yc[ci];
        part[tid] = a;
    }
    __syncthreads();
    if (tid < 128) zs[tid] = part[tid] + part[tid + 128];
    __syncthreads();

    if (tid < 32) {
        float s = zs[tid] + zs[tid + 32] + zs[tid + 64] + zs[tid + 96];
#pragma unroll
        for (int o = 16; o; o >>= 1) s += __shfl_xor_sync(0xffffffffu, s, o);
        if (tid == 0) red[0] = s * (1.0f / 128.0f);
    }
    __syncthreads();
    float mu = red[0];
    if (tid < 32) {
        float s = 0.0f;
#pragma unroll
        for (int q = 0; q < 4; ++q) { float dd = zs[tid + 32 * q] - mu; s += dd * dd; }
#pragma unroll
        for (int o = 16; o; o >>= 1) s += __shfl_xor_sync(0xffffffffu, s, o);
        if (tid == 0) red[1] = s * (1.0f / 128.0f);
    }
    __syncthreads();
    float rstd = rsqrtf(red[1] + 1e-5f);
    if (tid < 128) {
        float zn = (zs[tid] - mu) * rstd * lnw[tid] + lnb[tid];
        zs[tid] = 0.5f * zn * (1.0f + erff(zn * 0.70710678118654752f));
    }
    __syncthreads();

    // KV projection: output o = tid (0..127 -> k, 128..255 -> v), coalesced W
    float a = 0.0f;
    const float* wc = d_WkvT + tid;
#pragma unroll 8
    for (int ci = 0; ci < 128; ++ci) a += wc[ci * 256] * zs[ci];
    int m = (tid >> 4) & 7, d = tid & 15;
    float* dst = (tid < 128) ? d_k : d_v;
    dst[((size_t)(b * NH + m) * KVL + row) * HD + d] = a;
}

// ----------------------------------------------------------------------------
// K3: fused main kernel: one block per (b, image row y), 512 threads.
// thread layout: th = tid>>6 (head / 16-channel tile), tx = tid&63 (2 pixels)
// ----------------------------------------------------------------------------
#define STR   132
#define SWZ(c) ((c) & 28)
#define OFF_B (128 * STR)              // 16896
#define OFF_K (OFF_B + 128 * STR)      // 33792
#define OFF_V (OFF_K + NH * KVS)       // 44672
#define SMEMF (OFF_V + NH * KVS)       // 55552 floats = 222208 bytes

// out[x][o] = sum_c A[c*STR+x] * B[c][o^swz(c)]; acc[op][xi] packs (o=2op,2op+1)
__device__ __forceinline__ void gemm128x2(const float* __restrict__ A,
                                          const float* __restrict__ B,
                                          int tx, int th, u64 acc[8][2]) {
#pragma unroll
    for (int op = 0; op < 8; ++op) { acc[op][0] = 0ull; acc[op][1] = 0ull; }
    const float* ap = A + tx * 2;
    int base = th * 16;
#pragma unroll 4
    for (int k = 0; k < 128; ++k) {
        float2 av = *(const float2*)(ap + k * STR);
        const float* brow = B + k * STR;
        int s = SWZ(k);
        ulonglong2 b01 = *(const ulonglong2*)(brow + ((base     ) ^ s));
        ulonglong2 b23 = *(const ulonglong2*)(brow + ((base +  4) ^ s));
        ulonglong2 b45 = *(const ulonglong2*)(brow + ((base +  8) ^ s));
        ulonglong2 b67 = *(const ulonglong2*)(brow + ((base + 12) ^ s));
        u64 a0 = splat2(av.x), a1 = splat2(av.y);
        u64 bb[8] = {b01.x, b01.y, b23.x, b23.y, b45.x, b45.y, b67.x, b67.y};
#pragma unroll
        for (int op = 0; op < 8; ++op) {
            acc[op][0] = fma2(bb[op], a0, acc[op][0]);
            acc[op][1] = fma2(bb[op], a1, acc[op][1]);
        }
    }
}

__device__ __forceinline__ void load_w_swz(const float* __restrict__ W, float* __restrict__ Bs,
                                           int tid) {
    const float4* w4 = (const float4*)W;
    for (int i = tid; i < 4096; i += 512) {
        int o = i >> 5, cq = (i & 31) * 4;
        float4 w = w4[i];
        int col = o ^ SWZ(cq);   // (cq+d)&28 == cq&28 for d<4
        Bs[(cq    ) * STR + col] = w.x;
        Bs[(cq + 1) * STR + col] = w.y;
        Bs[(cq + 2) * STR + col] = w.z;
        Bs[(cq + 3) * STR + col] = w.w;
    }
}

__global__ void __launch_bounds__(512, 1)
k_main(const float* __restrict__ x, const float* __restrict__ Wq,
       const float* __restrict__ Wproj, const float* __restrict__ bproj,
       float* __restrict__ out) {
    extern __shared__ float sm[];
    float* As = sm;                // Xp (channel-major) then O
    float* Bs = sm + OFF_B;        // Wq(sw) -> Wproj(sw)
    float* Ks = sm + OFF_K;
    float* Vs = sm + OFF_V;
    int tid = threadIdx.x;
    int b = blockIdx.x >> 7;
    int y = blockIdx.x & 127;

    {   // K/V for this batch
        const float4* kg = (const float4*)(d_k + (size_t)b * NH * KVS);
        const float4* vg = (const float4*)(d_v + (size_t)b * NH * KVS);
        float4* k4 = (float4*)Ks;
        float4* v4 = (float4*)Vs;
        for (int i = tid; i < NH * KVS / 4; i += 512) { k4[i] = kg[i]; v4[i] = vg[i]; }
    }
    {   // Xp row (x + posenc), channel-major As[c*STR + xx]
        const float4* xr = (const float4*)(x + (((size_t)b * NC) << 14) + (y << 7));
        for (int i = tid; i < 4096; i += 512) {
            int c = i >> 5, xq = i & 31;
            float4 v = xr[c * 4096 + xq];
            if (c < 64) {
                float pe = d_tab[y * 64 + c];
                v.x += pe; v.y += pe; v.z += pe; v.w += pe;
            } else {
                float4 p = ((const float4*)d_tabT)[(c - 64) * 32 + xq];
                v.x += p.x; v.y += p.y; v.z += p.z; v.w += p.w;
            }
            *(float4*)(As + c * STR + xq * 4) = v;
        }
    }
    load_w_swz(Wq, Bs, tid);
    __syncthreads();

    int tx = tid & 63, th = tid >> 6;
    u64 acc[8][2];

    // ---- Q-GEMM ----
    gemm128x2(As, Bs, tx, th, acc);

    // acc[op][p] already IS pack2(Q[c=2op], Q[c=2op+1]) for pixel 2tx+p.
    // Fold in the hd^-0.5 = 0.25 scale; no smem round-trip needed.
    u64 q0[8], q1[8];
    {
        u64 s4 = splat2(0.25f);
#pragma unroll
        for (int op = 0; op < 8; ++op) {
            q0[op] = mul2(acc[op][0], s4);
            q1[op] = mul2(acc[op][1], s4);
        }
    }

    const u64* kb = (const u64*)(Ks + th * KVS);
    const u64* vb = (const u64*)(Vs + th * KVS);
    float* Os = As;   // Xp is dead after the GEMM (this thread read all it needs)
    __syncthreads();  // everyone done reading As/Bs before Os overwrites As

    // ---- attention: both pixels share each K/V load ----
    u64 oa0[8], oa1[8];
#pragma unroll
    for (int i = 0; i < 8; ++i) { oa0[i] = 0ull; oa1[i] = 0ull; }
    float s0 = 0.0f, s1 = 0.0f;
#pragma unroll 2
    for (int j = 0; j < KVL; ++j) {
        const float* kf = (const float*)(kb + j * 8);
        ulonglong2 k01 = *(const ulonglong2*)(kf);
        ulonglong2 k23 = *(const ulonglong2*)(kf + 4);
        ulonglong2 k45 = *(const ulonglong2*)(kf + 8);
        ulonglong2 k67 = *(const ulonglong2*)(kf + 12);
        u64 d00 = mul2(q0[0], k01.x), d01 = mul2(q0[1], k01.y);
        u64 d10 = mul2(q1[0], k01.x), d11 = mul2(q1[1], k01.y);
        d00 = fma2(q0[2], k23.x, d00);  d01 = fma2(q0[3], k23.y, d01);
        d10 = fma2(q1[2], k23.x, d10);  d11 = fma2(q1[3], k23.y, d11);
        d00 = fma2(q0[4], k45.x, d00);  d01 = fma2(q0[5], k45.y, d01);
        d10 = fma2(q1[4], k45.x, d10);  d11 = fma2(q1[5], k45.y, d11);
        d00 = fma2(q0[6], k67.x, d00);  d01 = fma2(q0[7], k67.y, d01);
        d10 = fma2(q1[6], k67.x, d10);  d11 = fma2(q1[7], k67.y, d11);
        float a0, b0, c0, e0l, a1f, b1f, c1f, e1l;
        unpack2(d00, a0, b0); unpack2(d01, c0, e0l);
        unpack2(d10, a1f, b1f); unpack2(d11, c1f, e1l);
        float e0 = __expf((a0 + b0) + (c0 + e0l));
        float e1 = __expf((a1f + b1f) + (c1f + e1l));
        s0 += e0; s1 += e1;
        u64 p0 = splat2(e0), p1 = splat2(e1);
        const float* vf = (const float*)(vb + j * 8);
        ulonglong2 v01 = *(const ulonglong2*)(vf);
        ulonglong2 v23 = *(const ulonglong2*)(vf + 4);
        ulonglong2 v45 = *(const ulonglong2*)(vf + 8);
        ulonglong2 v67 = *(const ulonglong2*)(vf + 12);
        oa0[0] = fma2(p0, v01.x, oa0[0]);  oa1[0] = fma2(p1, v01.x, oa1[0]);
        oa0[1] = fma2(p0, v01.y, oa0[1]);  oa1[1] = fma2(p1, v01.y, oa1[1]);
        oa0[2] = fma2(p0, v23.x, oa0[2]);  oa1[2] = fma2(p1, v23.x, oa1[2]);
        oa0[3] = fma2(p0, v23.y, oa0[3]);  oa1[3] = fma2(p1, v23.y, oa1[3]);
        oa0[4] = fma2(p0, v45.x, oa0[4]);  oa1[4] = fma2(p1, v45.x, oa1[4]);
        oa0[5] = fma2(p0, v45.y, oa0[5]);  oa1[5] = fma2(p1, v45.y, oa1[5]);
        oa0[6] = fma2(p0, v67.x, oa0[6]);  oa1[6] = fma2(p1, v67.x, oa1[6]);
        oa0[7] = fma2(p0, v67.y, oa0[7]);  oa1[7] = fma2(p1, v67.y, oa1[7]);
    }
    {
        float i0 = 1.0f / s0, i1 = 1.0f / s1;
        int xx = tx * 2;
#pragma unroll
        for (int i = 0; i < 8; ++i) {
            float lo, hi;
            unpack2(oa0[i], lo, hi);
            Os[(th * 16 + 2 * i) * STR + xx] = lo * i0;
            Os[(th * 16 + 2 * i + 1) * STR + xx] = hi * i0;
            unpack2(oa1[i], lo, hi);
            Os[(th * 16 + 2 * i) * STR + xx + 1] = lo * i1;
            Os[(th * 16 + 2 * i + 1) * STR + xx + 1] = hi * i1;
        }
    }
    __syncthreads();   // Os complete; Bs (Wq) dead

    // ---- out-proj GEMM ----
    load_w_swz(Wproj, Bs, tid);
    __syncthreads();
    gemm128x2(Os, Bs, tx, th, acc);

    float* og = out + (((size_t)b * NC) << 14) + (y << 7) + tx * 2;
#pragma unroll
    for (int op = 0; op < 8; ++op) {
        float b0 = bproj[th * 16 + 2 * op];
        float b1 = bproj[th * 16 + 2 * op + 1];
        float l0, h0, l1, h1;
        unpack2(acc[op][0], l0, h0);   // pixel 2tx:   channels 2op, 2op+1
        unpack2(acc[op][1], l1, h1);   // pixel 2tx+1: channels 2op, 2op+1
        *(float2*)(og + ((size_t)(th * 16 + 2 * op) << 14)) = make_float2(l0 + b0, l1 + b0);
        *(float2*)(og + ((size_t)(th * 16 + 2 * op + 1) << 14)) = make_float2(h0 + b1, h1 + b1);
    }
}

// ----------------------------------------------------------------------------
extern "C" void kernel_launch(void* const* d_in, const int* in_sizes, int n_in,
                              void* d_out, int out_size) {
    const float* x     = (const float*)d_in[0];
    const float* Wq    = (const float*)d_in[1];
    const float* Wkv   = (const float*)d_in[2];
    const float* Wproj = (const float*)d_in[3];
    const float* bproj = (const float*)d_in[4];
    const float* dw    = (const float*)d_in[5];
    const float* pw    = (const float*)d_in[6];
    const float* lnw   = (const float*)d_in[7];
    const float* lnb   = (const float*)d_in[8];
    float* out = (float*)d_out;

    cudaFuncSetAttribute(k_main, cudaFuncAttributeMaxDynamicSharedMemorySize,
                         SMEMF * (int)sizeof(float));

    k_tables<<<258, 256>>>(pw, Wkv);
    k_pool_dw<<<NB * NC, 256>>>(x, dw);
    k_pw_ln_kv<<<NB * KVL, 256>>>(lnw, lnb);
    k_main<<<NB * 128, 512, SMEMF * sizeof(float)>>>(x, Wq, Wproj, bproj, out);
}